// round 16
// baseline (speedup 1.0000x reference)
#include <cuda_runtime.h>
#include <math.h>

#define N_NODES 10000
#define N_EDGES 320000
#define ADJ_ROWS 80      // i-rows per adj block (125 * 80 == 10000)

// output region offsets in floats
#define OFF_NODE_EMB   0L
#define OFF_EDGE_EMB   80000L
#define OFF_RECON_NODE 2640000L
#define OFF_RECON_EDGE 3280000L
#define OFF_ADJ        13520000L
#define OFF_COORD      113520000L

__device__ float g_A[N_NODES * 128];          // nf @ W1[0:64]  + b1
__device__ float g_B[N_NODES * 128];          // nf @ W1[64:128]
__device__ float g_agg[N_NODES * 32];         // segment_sum(edge_out)
__device__ float g_emb[N_NODES * 8];          // node_emb copy for adj kernel
__device__ float g_r[N_NODES];                // ||node_emb||^2
__device__ __align__(16) float4 g_geo[N_EDGES]; // d0,d1,d2,radial per edge

__device__ __forceinline__ unsigned cvt_tf32(float x) {
    unsigned r;
    asm("cvt.rna.tf32.f32 %0, %1;" : "=r"(r) : "f"(x));
    return r;
}

#define MMA_TF32(d0, d1, d2, d3, a0, a1, a2, a3, b0, b1)                     \
    asm volatile(                                                            \
        "mma.sync.aligned.m16n8k8.row.col.f32.tf32.tf32.f32 "                \
        "{%0,%1,%2,%3}, {%4,%5,%6,%7}, {%8,%9}, {%0,%1,%2,%3};"              \
        : "+f"(d0), "+f"(d1), "+f"(d2), "+f"(d3)                             \
        : "r"(a0), "r"(a1), "r"(a2), "r"(a3), "r"(b0), "r"(b1))

// ---------------------------------------------------------------------------
// K_pre: blocks 0..591 -> A proj, 592..1183 -> B proj,
//        1184..3683 -> init (agg zero, geo precompute, coord copy)
// ---------------------------------------------------------------------------
__global__ __launch_bounds__(128) void k_pre(
        const float* __restrict__ nf, const float* __restrict__ ew1,
        const float* __restrict__ eb1,
        const int* __restrict__ ei, const float* __restrict__ coords,
        float* __restrict__ out) {
    int bid = blockIdx.x;
    int tid = threadIdx.x;
    if (bid < 1184) {
        __shared__ float ws[64 * 128];
        __shared__ float xs[64];
        int which = bid >= 592;
        int b0 = which ? bid - 592 : bid;
        const float* w = ew1 + (which ? 64 * 128 : 0);
        float* dst = which ? g_B : g_A;
        for (int i = tid; i < 64 * 128; i += 128) ws[i] = w[i];
        float bias = which ? 0.f : eb1[tid];
        __syncthreads();
        for (int n = b0; n < N_NODES; n += 592) {
            if (tid < 64) xs[tid] = nf[n * 64 + tid];
            __syncthreads();
            float acc = bias;
#pragma unroll
            for (int f = 0; f < 64; f++) acc = fmaf(xs[f], ws[f * 128 + tid], acc);
            dst[n * 128 + tid] = acc;
            __syncthreads();
        }
    } else {
        int i = (bid - 1184) * 128 + tid;    // 0..319999 exactly
        g_agg[i] = 0.f;                      // N_NODES*32 == N_EDGES
        int r = ei[i], c = ei[N_EDGES + i];
        float d0 = coords[r * 3 + 0] - coords[c * 3 + 0];
        float d1 = coords[r * 3 + 1] - coords[c * 3 + 1];
        float d2 = coords[r * 3 + 2] - coords[c * 3 + 2];
        g_geo[i] = make_float4(d0, d1, d2, d0 * d0 + d1 * d1 + d2 * d2);
        if (i < N_NODES * 3) out[OFF_COORD + i] = coords[i];
    }
}

// ---------------------------------------------------------------------------
// K2: tf32 mma edge kernel, coalesced operand staging (R13 structure),
// occupancy raised to 5 blocks/SM.
// 128 threads = 4 warps; 16 edges per tile; warp w owns n/k-slice [32w,32w+32).
// ---------------------------------------------------------------------------
__global__ __launch_bounds__(128, 5) void k_edge_fused(
        const float* __restrict__ ew1,  // [161,128]
        const float* __restrict__ ew2, const float* __restrict__ eb2,
        const float* __restrict__ cw1, const float* __restrict__ cb1,
        const float* __restrict__ cw2,
        const float* __restrict__ few, const float* __restrict__ feb,
        const float* __restrict__ dew, const float* __restrict__ deb,
        const int* __restrict__ ei, const float* __restrict__ ea,
        float* __restrict__ out) {
    __shared__ __align__(16) float seas[16][36];   // ea staged
    __shared__ __align__(16) float sAB[16][136];   // fp32-exact accum init
    __shared__ float hs[16][132];
    __shared__ float part[16][4][34];
    __shared__ float ovs[16][32];
    __shared__ float ers[16][8];
    __shared__ __align__(16) float s_fwT[10][36];
    __shared__ float s_b2[32], s_fcb[8], s_dew[256], s_deb[32], s_misc[4];

    int tid = threadIdx.x;
    int w = tid >> 5, lane = tid & 31;
    int g4 = lane >> 2, c4 = lane & 3;
    int j = lane;

    if (tid < 32) { s_b2[tid] = eb2[tid]; s_deb[tid] = deb[tid]; }
    for (int x = tid; x < 320; x += 128) {
        int r = x >> 5, jj = x & 31;
        s_fwT[r][jj] = (r < 8) ? few[jj * 8 + r] : cw1[jj * 2 + (r - 8)];
    }
    for (int x = tid; x < 256; x += 128) s_dew[x] = dew[x];
    if (tid < 8)  s_fcb[tid] = feb[tid];
    if (tid == 0) { s_misc[0] = cb1[0]; s_misc[1] = cb1[1]; s_misc[2] = cw2[0]; s_misc[3] = cw2[1]; }

    // B fragments: W1e [32 x 128], warp n-slice 32w..32w+32 (4 ntiles of 8)
    unsigned b1[4][4][2];
#pragma unroll
    for (int ks = 0; ks < 4; ks++)
#pragma unroll
        for (int t = 0; t < 4; t++) {
            int k = ks * 8 + c4, n = 32 * w + t * 8 + g4;
            b1[ks][t][0] = cvt_tf32(ew1[(128 + k) * 128 + n]);
            b1[ks][t][1] = cvt_tf32(ew1[(128 + k + 4) * 128 + n]);
        }
    // B fragments: W2 [128 x 32], warp k-slice 32w..32w+32, N=32 (4 ntiles)
    unsigned b2[4][4][2];
#pragma unroll
    for (int ks = 0; ks < 4; ks++)
#pragma unroll
        for (int t = 0; t < 4; t++) {
            int k = 32 * w + ks * 8 + c4, jn = t * 8 + g4;
            b2[ks][t][0] = cvt_tf32(ew2[k * 32 + jn]);
            b2[ks][t][1] = cvt_tf32(ew2[(k + 4) * 32 + jn]);
        }
    float w1rcol = ew1[160 * 128 + 32 * w + lane];   // this lane's w1r column
    __syncthreads();

    const int ie8 = tid >> 3, cf = tid & 7;
    const long stride = (long)gridDim.x * 16;
    for (long base = (long)blockIdx.x * 16; base < N_EDGES; base += stride) {
        // ---- edge indices + radial (per warp; L1-served) ----
        int iv = (lane < 16) ? ei[base + lane] : ei[N_EDGES + base + lane - 16];
        float gw = 0.f;
        if (lane < 16) gw = g_geo[base + lane].w;

        // ---- stage ea (block-cooperative, coalesced float4) ----
        {
            float4 v = *(const float4*)(ea + (base + ie8) * 32 + cf * 4);
            *(float4*)&seas[ie8][cf * 4] = v;
        }
        // ---- build sAB: coalesced 128B row gathers, conflict-free STS ----
#pragma unroll
        for (int i = 0; i < 16; i++) {
            int ri = __shfl_sync(0xffffffffu, iv, i);
            int ci = __shfl_sync(0xffffffffu, iv, 16 + i);
            float radi = __shfl_sync(0xffffffffu, gw, i);
            sAB[i][32 * w + lane] = g_A[(long)ri * 128 + 32 * w + lane]
                                  + g_B[(long)ci * 128 + 32 * w + lane]
                                  + radi * w1rcol;
        }
        __syncthreads();   // seas + sAB ready; part(n-1) reads done

        // ---- layer-1: accum init from sAB, mma over seas ----
        float d[4][4];
#pragma unroll
        for (int t = 0; t < 4; t++) {
            int n0 = 32 * w + t * 8 + 2 * c4;
            float2 lo = *(const float2*)&sAB[g4][n0];
            float2 hi = *(const float2*)&sAB[g4 + 8][n0];
            d[t][0] = lo.x; d[t][1] = lo.y; d[t][2] = hi.x; d[t][3] = hi.y;
        }
#pragma unroll
        for (int ks = 0; ks < 4; ks++) {
            unsigned a0 = cvt_tf32(seas[g4][ks * 8 + c4]);
            unsigned a1 = cvt_tf32(seas[g4 + 8][ks * 8 + c4]);
            unsigned a2 = cvt_tf32(seas[g4][ks * 8 + c4 + 4]);
            unsigned a3 = cvt_tf32(seas[g4 + 8][ks * 8 + c4 + 4]);
#pragma unroll
            for (int t = 0; t < 4; t++)
                MMA_TF32(d[t][0], d[t][1], d[t][2], d[t][3],
                         a0, a1, a2, a3, b1[ks][t][0], b1[ks][t][1]);
        }

        // ---- relu -> hs ----
#pragma unroll
        for (int t = 0; t < 4; t++) {
            int n0 = 32 * w + t * 8 + 2 * c4;
            *(float2*)&hs[g4][n0]     = make_float2(fmaxf(d[t][0], 0.f), fmaxf(d[t][1], 0.f));
            *(float2*)&hs[g4 + 8][n0] = make_float2(fmaxf(d[t][2], 0.f), fmaxf(d[t][3], 0.f));
        }
        __syncthreads();   // hs ready

        // ---- layer-2 mma: partial over this warp's 32-k slice ----
        float e2[4][4];
#pragma unroll
        for (int t = 0; t < 4; t++)
            e2[t][0] = e2[t][1] = e2[t][2] = e2[t][3] = 0.f;
#pragma unroll
        for (int ks = 0; ks < 4; ks++) {
            int kk = 32 * w + ks * 8 + c4;
            unsigned a0 = cvt_tf32(hs[g4][kk]);
            unsigned a1 = cvt_tf32(hs[g4 + 8][kk]);
            unsigned a2 = cvt_tf32(hs[g4][kk + 4]);
            unsigned a3 = cvt_tf32(hs[g4 + 8][kk + 4]);
#pragma unroll
            for (int t = 0; t < 4; t++)
                MMA_TF32(e2[t][0], e2[t][1], e2[t][2], e2[t][3],
                         a0, a1, a2, a3, b2[ks][t][0], b2[ks][t][1]);
        }
#pragma unroll
        for (int t = 0; t < 4; t++) {
            int j0 = t * 8 + 2 * c4;
            *(float2*)&part[g4][w][j0]     = make_float2(e2[t][0], e2[t][1]);
            *(float2*)&part[g4 + 8][w][j0] = make_float2(e2[t][2], e2[t][3]);
        }
        __syncthreads();   // part ready

        // ---- epilogue: warp w handles edges 4w..4w+3 ----
#pragma unroll
        for (int s = 0; s < 4; s++) {
            int eidx = w * 4 + s;
            long e = base + eidx;
            float ov = part[eidx][0][j] + part[eidx][1][j]
                     + part[eidx][2][j] + part[eidx][3][j] + s_b2[j];
            int row = __shfl_sync(0xffffffffu, iv, eidx);
            ovs[eidx][j] = ov;
            float o1 = __shfl_down_sync(0xffffffffu, ov, 1);
            float o2 = __shfl_down_sync(0xffffffffu, ov, 2);
            float o3 = __shfl_down_sync(0xffffffffu, ov, 3);
            if ((j & 3) == 0) {
                asm volatile("red.global.add.v4.f32 [%0], {%1, %2, %3, %4};"
                             :: "l"(g_agg + row * 32 + j),
                                "f"(ov), "f"(o1), "f"(o2), "f"(o3)
                             : "memory");
            }
            __syncwarp();
            float acc = 0.f;
            if (j < 10) {
                const float4* ovv = (const float4*)ovs[eidx];
#pragma unroll
                for (int q = 0; q < 8; q++) {
                    float4 v = ovv[q];
                    acc = fmaf(v.x, s_fwT[j][q * 4 + 0], acc);
                    acc = fmaf(v.y, s_fwT[j][q * 4 + 1], acc);
                    acc = fmaf(v.z, s_fwT[j][q * 4 + 2], acc);
                    acc = fmaf(v.w, s_fwT[j][q * 4 + 3], acc);
                }
            }
            if (j < 8) {
                float er = acc + s_fcb[j];
                out[OFF_EDGE_EMB + e * 8 + j] = er;
                ers[eidx][j] = er;
            }
            float q8 = __shfl_sync(0xffffffffu, acc, 8);
            float q9 = __shfl_sync(0xffffffffu, acc, 9);
            __syncwarp();
            float4 e0 = ((const float4*)ers[eidx])[0];
            float4 e1 = ((const float4*)ers[eidx])[1];
            float rec = s_deb[j];
            rec = fmaf(e0.x, s_dew[0 * 32 + j], rec);
            rec = fmaf(e0.y, s_dew[1 * 32 + j], rec);
            rec = fmaf(e0.z, s_dew[2 * 32 + j], rec);
            rec = fmaf(e0.w, s_dew[3 * 32 + j], rec);
            rec = fmaf(e1.x, s_dew[4 * 32 + j], rec);
            rec = fmaf(e1.y, s_dew[5 * 32 + j], rec);
            rec = fmaf(e1.z, s_dew[6 * 32 + j], rec);
            rec = fmaf(e1.w, s_dew[7 * 32 + j], rec);
            out[OFF_RECON_EDGE + e * 32 + j] = rec;
            if (j < 3) {
                float4 gg = g_geo[e];
                float wz = fmaxf(q8 + s_misc[0], 0.f) * s_misc[2] +
                           fmaxf(q9 + s_misc[1], 0.f) * s_misc[3];
                float inv = 1.0f / (sqrtf(gg.w) + 1.0f);
                float dj = (j == 0) ? gg.x : (j == 1) ? gg.y : gg.z;
                atomicAdd(out + OFF_COORD + row * 3 + j, dj * inv * wz);
            }
        }
    }
}

// ---------------------------------------------------------------------------
// K_node: fused node layer-1 + layer-2 + epilogue.  256 threads, 2 nodes/iter.
// ---------------------------------------------------------------------------
__global__ __launch_bounds__(256) void k_node(
        const float* __restrict__ nw1, const float* __restrict__ nb1,
        const float* __restrict__ nf, const float* __restrict__ outc,
        const float* __restrict__ nw2, const float* __restrict__ nb2,
        const float* __restrict__ fnw, const float* __restrict__ fnb,
        const float* __restrict__ dnw, const float* __restrict__ dnb,
        float* __restrict__ out) {
    __shared__ __align__(16) float hs2[2][128];
    __shared__ float ps[2][2][8];
    int tid = threadIdx.x;
    int k = tid & 127, slot1 = tid >> 7, lane = tid & 31;
    float bias1 = nb1[k];
    float wc0 = nw1[96 * 128 + k], wc1 = nw1[97 * 128 + k], wc2 = nw1[98 * 128 + k];
    int slot2 = (tid >> 6) & 1, jj = tid & 63, half = (tid >> 5) & 1;
    float bias2 = nb2[jj];

    for (int n0 = blockIdx.x * 2; n0 < N_NODES; n0 += gridDim.x * 2) {
        int n = n0 + slot1;
        float xa = nf[n * 64 + lane];
        float xb = nf[n * 64 + 32 + lane];
        float xc = g_agg[n * 32 + lane];
        float h = bias1;
#pragma unroll
        for (int t = 0; t < 32; t++)
            h = fmaf(__shfl_sync(0xffffffffu, xa, t), __ldg(nw1 + t * 128 + k), h);
#pragma unroll
        for (int t = 0; t < 32; t++)
            h = fmaf(__shfl_sync(0xffffffffu, xb, t), __ldg(nw1 + (32 + t) * 128 + k), h);
#pragma unroll
        for (int t = 0; t < 32; t++)
            h = fmaf(__shfl_sync(0xffffffffu, xc, t), __ldg(nw1 + (64 + t) * 128 + k), h);
        h = fmaf(outc[n * 3 + 0], wc0, h);
        h = fmaf(outc[n * 3 + 1], wc1, h);
        h = fmaf(outc[n * 3 + 2], wc2, h);
        hs2[slot1][k] = fmaxf(h, 0.f);
        __syncthreads();

        int n2 = n0 + slot2;
        float acc = bias2;
        if (tid < 128) {
            const float4* hrow = (const float4*)hs2[slot2];
#pragma unroll 8
            for (int kq = 0; kq < 32; kq++) {
                float4 v = hrow[kq];
                acc = fmaf(v.x, __ldg(nw2 + (kq * 4 + 0) * 64 + jj), acc);
                acc = fmaf(v.y, __ldg(nw2 + (kq * 4 + 1) * 64 + jj), acc);
                acc = fmaf(v.z, __ldg(nw2 + (kq * 4 + 2) * 64 + jj), acc);
                acc = fmaf(v.w, __ldg(nw2 + (kq * 4 + 3) * 64 + jj), acc);
            }
            float p[8];
#pragma unroll
            for (int r = 0; r < 8; r++) p[r] = acc * __ldg(fnw + jj * 8 + r);
#pragma unroll
            for (int off = 16; off > 0; off >>= 1) {
#pragma unroll
                for (int r = 0; r < 8; r++) p[r] += __shfl_xor_sync(0xffffffffu, p[r], off);
            }
            if (lane == 0) {
#pragma unroll
                for (int r = 0; r < 8; r++) ps[slot2][half][r] = p[r];
            }
        }
        __syncthreads();
        if (tid < 128) {
            float er[8];
#pragma unroll
            for (int r = 0; r < 8; r++)
                er[r] = ps[slot2][0][r] + ps[slot2][1][r] + __ldg(fnb + r);
            if (jj == 0) {
                float4 v0 = make_float4(er[0], er[1], er[2], er[3]);
                float4 v1 = make_float4(er[4], er[5], er[6], er[7]);
                ((float4*)(out + OFF_NODE_EMB + (long)n2 * 8))[0] = v0;
                ((float4*)(out + OFF_NODE_EMB + (long)n2 * 8))[1] = v1;
                ((float4*)(g_emb + n2 * 8))[0] = v0;
                ((float4*)(g_emb + n2 * 8))[1] = v1;
                float rr = 0.f;
#pragma unroll
                for (int r = 0; r < 8; r++) rr = fmaf(er[r], er[r], rr);
                g_r[n2] = rr;
            }
            float rec = __ldg(dnb + jj);
#pragma unroll
            for (int r = 0; r < 8; r++) rec = fmaf(er[r], __ldg(dnw + r * 64 + jj), rec);
            out[OFF_RECON_NODE + (long)n2 * 64 + jj] = rec;
        }
        __syncthreads();
    }
}

// ---------------------------------------------------------------------------
// K_adj: 80 rows x 1024 cols per block; folded sigmoid (1 MUFU).
// (R13 diagonal handling: per-quad select — R15 overwrite variant regressed.)
// ---------------------------------------------------------------------------
__global__ __launch_bounds__(256) void k_adj(float* __restrict__ out) {
    int tid = threadIdx.x;
    int j0 = blockIdx.x * 1024 + tid * 4;
    float ejs[4][8], cj[4];
#pragma unroll
    for (int q = 0; q < 4; q++) {
        int jx = j0 + q;
        if (jx < N_NODES) {
            float4 a = ((const float4*)(g_emb + jx * 8))[0];
            float4 b = ((const float4*)(g_emb + jx * 8))[1];
            ejs[q][0] = -3.f * a.x; ejs[q][1] = -3.f * a.y;
            ejs[q][2] = -3.f * a.z; ejs[q][3] = -3.f * a.w;
            ejs[q][4] = -3.f * b.x; ejs[q][5] = -3.f * b.y;
            ejs[q][6] = -3.f * b.z; ejs[q][7] = -3.f * b.w;
            cj[q] = fmaf(1.5f, g_r[jx], -0.5f);
        } else {
#pragma unroll
            for (int r = 0; r < 8; r++) ejs[q][r] = 0.f;
            cj[q] = -0.5f;
        }
    }
    int ibase = blockIdx.y * ADJ_ROWS;   // 125 * 80 == 10000 exactly
    for (int ii = 0; ii < ADJ_ROWS; ii++) {
        int i = ibase + ii;
        float4 a = ((const float4*)(g_emb + i * 8))[0];
        float4 b = ((const float4*)(g_emb + i * 8))[1];
        float eiv[8] = {a.x, a.y, a.z, a.w, b.x, b.y, b.z, b.w};
        float ai = 1.5f * g_r[i];
        float res[4];
#pragma unroll
        for (int q = 0; q < 4; q++) {
            float acc = ai + cj[q];
#pragma unroll
            for (int r = 0; r < 8; r++) acc = fmaf(eiv[r], ejs[q][r], acc);
            float t;
            asm("tanh.approx.f32 %0, %1;" : "=f"(t) : "f"(acc));
            float v = fmaf(0.5f, t, 0.5f);
            res[q] = (j0 + q == i) ? 0.f : v;
        }
        if (j0 < N_NODES) {
            __stcs((float4*)(out + OFF_ADJ + (long)i * N_NODES + j0),
                   make_float4(res[0], res[1], res[2], res[3]));
        }
    }
}

// ---------------------------------------------------------------------------
extern "C" void kernel_launch(void* const* d_in, const int* in_sizes, int n_in,
                              void* d_out, int out_size) {
    const float* nf     = (const float*)d_in[0];
    const int*   ei     = (const int*)  d_in[1];
    const float* ea     = (const float*)d_in[2];
    const float* coords = (const float*)d_in[3];
    const float* ew1    = (const float*)d_in[4];
    const float* eb1    = (const float*)d_in[5];
    const float* ew2    = (const float*)d_in[6];
    const float* eb2    = (const float*)d_in[7];
    const float* cw1    = (const float*)d_in[8];
    const float* cb1    = (const float*)d_in[9];
    const float* cw2    = (const float*)d_in[10];
    const float* nw1    = (const float*)d_in[11];
    const float* nb1    = (const float*)d_in[12];
    const float* nw2    = (const float*)d_in[13];
    const float* nb2    = (const float*)d_in[14];
    const float* fnw    = (const float*)d_in[15];
    const float* fnb    = (const float*)d_in[16];
    const float* few    = (const float*)d_in[17];
    const float* feb    = (const float*)d_in[18];
    const float* dnw    = (const float*)d_in[19];
    const float* dnb    = (const float*)d_in[20];
    const float* dew    = (const float*)d_in[21];
    const float* deb    = (const float*)d_in[22];
    float* out = (float*)d_out;

    k_pre<<<1184 + 2500, 128>>>(nf, ew1, eb1, ei, coords, out);
    k_edge_fused<<<740, 128>>>(ew1, ew2, eb2, cw1, cb1, cw2, few, feb, dew, deb,
                               ei, ea, out);
    k_node<<<592, 256>>>(nw1, nb1, nf, out + OFF_COORD, nw2, nb2,
                         fnw, fnb, dnw, dnb, out);
    dim3 gadj(10, N_NODES / ADJ_ROWS);
    k_adj<<<gadj, 256>>>(out);
}

// round 17
// speedup vs baseline: 1.0369x; 1.0369x over previous
#include <cuda_runtime.h>
#include <math.h>

#define N_NODES 10000
#define N_EDGES 320000
#define ADJ_ROWS 80      // i-rows per adj block (125 * 80 == 10000)

// output region offsets in floats
#define OFF_NODE_EMB   0L
#define OFF_EDGE_EMB   80000L
#define OFF_RECON_NODE 2640000L
#define OFF_RECON_EDGE 3280000L
#define OFF_ADJ        13520000L
#define OFF_COORD      113520000L

__device__ float g_A[N_NODES * 128];          // nf @ W1[0:64]  + b1
__device__ float g_B[N_NODES * 128];          // nf @ W1[64:128]
__device__ float g_agg[N_NODES * 32];         // segment_sum(edge_out)
__device__ float g_emb[N_NODES * 8];          // node_emb copy for adj kernel
__device__ float g_r[N_NODES];                // ||node_emb||^2
__device__ __align__(16) float4 g_geo[N_EDGES]; // d0,d1,d2,radial per edge

__device__ __forceinline__ unsigned cvt_tf32(float x) {
    unsigned r;
    asm("cvt.rna.tf32.f32 %0, %1;" : "=r"(r) : "f"(x));
    return r;
}

#define MMA_TF32(d0, d1, d2, d3, a0, a1, a2, a3, b0, b1)                     \
    asm volatile(                                                            \
        "mma.sync.aligned.m16n8k8.row.col.f32.tf32.tf32.f32 "                \
        "{%0,%1,%2,%3}, {%4,%5,%6,%7}, {%8,%9}, {%0,%1,%2,%3};"              \
        : "+f"(d0), "+f"(d1), "+f"(d2), "+f"(d3)                             \
        : "r"(a0), "r"(a1), "r"(a2), "r"(a3), "r"(b0), "r"(b1))

// ---------------------------------------------------------------------------
// K_pre: blocks 0..591 -> A proj, 592..1183 -> B proj,
//        1184..3683 -> init (agg zero, geo precompute, coord copy)
// ---------------------------------------------------------------------------
__global__ __launch_bounds__(128) void k_pre(
        const float* __restrict__ nf, const float* __restrict__ ew1,
        const float* __restrict__ eb1,
        const int* __restrict__ ei, const float* __restrict__ coords,
        float* __restrict__ out) {
    int bid = blockIdx.x;
    int tid = threadIdx.x;
    if (bid < 1184) {
        __shared__ float ws[64 * 128];
        __shared__ float xs[64];
        int which = bid >= 592;
        int b0 = which ? bid - 592 : bid;
        const float* w = ew1 + (which ? 64 * 128 : 0);
        float* dst = which ? g_B : g_A;
        for (int i = tid; i < 64 * 128; i += 128) ws[i] = w[i];
        float bias = which ? 0.f : eb1[tid];
        __syncthreads();
        for (int n = b0; n < N_NODES; n += 592) {
            if (tid < 64) xs[tid] = nf[n * 64 + tid];
            __syncthreads();
            float acc = bias;
#pragma unroll
            for (int f = 0; f < 64; f++) acc = fmaf(xs[f], ws[f * 128 + tid], acc);
            dst[n * 128 + tid] = acc;
            __syncthreads();
        }
    } else {
        int i = (bid - 1184) * 128 + tid;    // 0..319999 exactly
        g_agg[i] = 0.f;                      // N_NODES*32 == N_EDGES
        int r = ei[i], c = ei[N_EDGES + i];
        float d0 = coords[r * 3 + 0] - coords[c * 3 + 0];
        float d1 = coords[r * 3 + 1] - coords[c * 3 + 1];
        float d2 = coords[r * 3 + 2] - coords[c * 3 + 2];
        g_geo[i] = make_float4(d0, d1, d2, d0 * d0 + d1 * d1 + d2 * d2);
        if (i < N_NODES * 3) out[OFF_COORD + i] = coords[i];
    }
}

// ---------------------------------------------------------------------------
// K2: tf32 mma edge kernel, coalesced operand staging (exact R13 config:
// 4 blocks/SM, grid 592 = one full wave).
// 128 threads = 4 warps; 16 edges per tile; warp w owns n/k-slice [32w,32w+32).
// ---------------------------------------------------------------------------
__global__ __launch_bounds__(128, 4) void k_edge_fused(
        const float* __restrict__ ew1,  // [161,128]
        const float* __restrict__ ew2, const float* __restrict__ eb2,
        const float* __restrict__ cw1, const float* __restrict__ cb1,
        const float* __restrict__ cw2,
        const float* __restrict__ few, const float* __restrict__ feb,
        const float* __restrict__ dew, const float* __restrict__ deb,
        const int* __restrict__ ei, const float* __restrict__ ea,
        float* __restrict__ out) {
    __shared__ __align__(16) float seas[16][36];   // ea staged
    __shared__ __align__(16) float sAB[16][136];   // fp32-exact accum init
    __shared__ float hs[16][132];
    __shared__ float part[16][4][34];
    __shared__ float ovs[16][32];
    __shared__ float ers[16][8];
    __shared__ __align__(16) float s_fwT[10][36];
    __shared__ float s_b2[32], s_fcb[8], s_dew[256], s_deb[32], s_misc[4];

    int tid = threadIdx.x;
    int w = tid >> 5, lane = tid & 31;
    int g4 = lane >> 2, c4 = lane & 3;
    int j = lane;

    if (tid < 32) { s_b2[tid] = eb2[tid]; s_deb[tid] = deb[tid]; }
    for (int x = tid; x < 320; x += 128) {
        int r = x >> 5, jj = x & 31;
        s_fwT[r][jj] = (r < 8) ? few[jj * 8 + r] : cw1[jj * 2 + (r - 8)];
    }
    for (int x = tid; x < 256; x += 128) s_dew[x] = dew[x];
    if (tid < 8)  s_fcb[tid] = feb[tid];
    if (tid == 0) { s_misc[0] = cb1[0]; s_misc[1] = cb1[1]; s_misc[2] = cw2[0]; s_misc[3] = cw2[1]; }

    // B fragments: W1e [32 x 128], warp n-slice 32w..32w+32 (4 ntiles of 8)
    unsigned b1[4][4][2];
#pragma unroll
    for (int ks = 0; ks < 4; ks++)
#pragma unroll
        for (int t = 0; t < 4; t++) {
            int k = ks * 8 + c4, n = 32 * w + t * 8 + g4;
            b1[ks][t][0] = cvt_tf32(ew1[(128 + k) * 128 + n]);
            b1[ks][t][1] = cvt_tf32(ew1[(128 + k + 4) * 128 + n]);
        }
    // B fragments: W2 [128 x 32], warp k-slice 32w..32w+32, N=32 (4 ntiles)
    unsigned b2[4][4][2];
#pragma unroll
    for (int ks = 0; ks < 4; ks++)
#pragma unroll
        for (int t = 0; t < 4; t++) {
            int k = 32 * w + ks * 8 + c4, jn = t * 8 + g4;
            b2[ks][t][0] = cvt_tf32(ew2[k * 32 + jn]);
            b2[ks][t][1] = cvt_tf32(ew2[(k + 4) * 32 + jn]);
        }
    float w1rcol = ew1[160 * 128 + 32 * w + lane];   // this lane's w1r column
    __syncthreads();

    const int ie8 = tid >> 3, cf = tid & 7;
    const long stride = (long)gridDim.x * 16;
    for (long base = (long)blockIdx.x * 16; base < N_EDGES; base += stride) {
        // ---- edge indices + radial (per warp; L1-served) ----
        int iv = (lane < 16) ? ei[base + lane] : ei[N_EDGES + base + lane - 16];
        float gw = 0.f;
        if (lane < 16) gw = g_geo[base + lane].w;

        // ---- stage ea (block-cooperative, coalesced float4) ----
        {
            float4 v = *(const float4*)(ea + (base + ie8) * 32 + cf * 4);
            *(float4*)&seas[ie8][cf * 4] = v;
        }
        // ---- build sAB: coalesced 128B row gathers, conflict-free STS ----
#pragma unroll
        for (int i = 0; i < 16; i++) {
            int ri = __shfl_sync(0xffffffffu, iv, i);
            int ci = __shfl_sync(0xffffffffu, iv, 16 + i);
            float radi = __shfl_sync(0xffffffffu, gw, i);
            sAB[i][32 * w + lane] = g_A[(long)ri * 128 + 32 * w + lane]
                                  + g_B[(long)ci * 128 + 32 * w + lane]
                                  + radi * w1rcol;
        }
        __syncthreads();   // seas + sAB ready; part(n-1) reads done

        // ---- layer-1: accum init from sAB, mma over seas ----
        float d[4][4];
#pragma unroll
        for (int t = 0; t < 4; t++) {
            int n0 = 32 * w + t * 8 + 2 * c4;
            float2 lo = *(const float2*)&sAB[g4][n0];
            float2 hi = *(const float2*)&sAB[g4 + 8][n0];
            d[t][0] = lo.x; d[t][1] = lo.y; d[t][2] = hi.x; d[t][3] = hi.y;
        }
#pragma unroll
        for (int ks = 0; ks < 4; ks++) {
            unsigned a0 = cvt_tf32(seas[g4][ks * 8 + c4]);
            unsigned a1 = cvt_tf32(seas[g4 + 8][ks * 8 + c4]);
            unsigned a2 = cvt_tf32(seas[g4][ks * 8 + c4 + 4]);
            unsigned a3 = cvt_tf32(seas[g4 + 8][ks * 8 + c4 + 4]);
#pragma unroll
            for (int t = 0; t < 4; t++)
                MMA_TF32(d[t][0], d[t][1], d[t][2], d[t][3],
                         a0, a1, a2, a3, b1[ks][t][0], b1[ks][t][1]);
        }

        // ---- relu -> hs ----
#pragma unroll
        for (int t = 0; t < 4; t++) {
            int n0 = 32 * w + t * 8 + 2 * c4;
            *(float2*)&hs[g4][n0]     = make_float2(fmaxf(d[t][0], 0.f), fmaxf(d[t][1], 0.f));
            *(float2*)&hs[g4 + 8][n0] = make_float2(fmaxf(d[t][2], 0.f), fmaxf(d[t][3], 0.f));
        }
        __syncthreads();   // hs ready

        // ---- layer-2 mma: partial over this warp's 32-k slice ----
        float e2[4][4];
#pragma unroll
        for (int t = 0; t < 4; t++)
            e2[t][0] = e2[t][1] = e2[t][2] = e2[t][3] = 0.f;
#pragma unroll
        for (int ks = 0; ks < 4; ks++) {
            int kk = 32 * w + ks * 8 + c4;
            unsigned a0 = cvt_tf32(hs[g4][kk]);
            unsigned a1 = cvt_tf32(hs[g4 + 8][kk]);
            unsigned a2 = cvt_tf32(hs[g4][kk + 4]);
            unsigned a3 = cvt_tf32(hs[g4 + 8][kk + 4]);
#pragma unroll
            for (int t = 0; t < 4; t++)
                MMA_TF32(e2[t][0], e2[t][1], e2[t][2], e2[t][3],
                         a0, a1, a2, a3, b2[ks][t][0], b2[ks][t][1]);
        }
#pragma unroll
        for (int t = 0; t < 4; t++) {
            int j0 = t * 8 + 2 * c4;
            *(float2*)&part[g4][w][j0]     = make_float2(e2[t][0], e2[t][1]);
            *(float2*)&part[g4 + 8][w][j0] = make_float2(e2[t][2], e2[t][3]);
        }
        __syncthreads();   // part ready

        // ---- epilogue: warp w handles edges 4w..4w+3 ----
#pragma unroll
        for (int s = 0; s < 4; s++) {
            int eidx = w * 4 + s;
            long e = base + eidx;
            float ov = part[eidx][0][j] + part[eidx][1][j]
                     + part[eidx][2][j] + part[eidx][3][j] + s_b2[j];
            int row = __shfl_sync(0xffffffffu, iv, eidx);
            ovs[eidx][j] = ov;
            float o1 = __shfl_down_sync(0xffffffffu, ov, 1);
            float o2 = __shfl_down_sync(0xffffffffu, ov, 2);
            float o3 = __shfl_down_sync(0xffffffffu, ov, 3);
            if ((j & 3) == 0) {
                asm volatile("red.global.add.v4.f32 [%0], {%1, %2, %3, %4};"
                             :: "l"(g_agg + row * 32 + j),
                                "f"(ov), "f"(o1), "f"(o2), "f"(o3)
                             : "memory");
            }
            __syncwarp();
            float acc = 0.f;
            if (j < 10) {
                const float4* ovv = (const float4*)ovs[eidx];
#pragma unroll
                for (int q = 0; q < 8; q++) {
                    float4 v = ovv[q];
                    acc = fmaf(v.x, s_fwT[j][q * 4 + 0], acc);
                    acc = fmaf(v.y, s_fwT[j][q * 4 + 1], acc);
                    acc = fmaf(v.z, s_fwT[j][q * 4 + 2], acc);
                    acc = fmaf(v.w, s_fwT[j][q * 4 + 3], acc);
                }
            }
            if (j < 8) {
                float er = acc + s_fcb[j];
                out[OFF_EDGE_EMB + e * 8 + j] = er;
                ers[eidx][j] = er;
            }
            float q8 = __shfl_sync(0xffffffffu, acc, 8);
            float q9 = __shfl_sync(0xffffffffu, acc, 9);
            __syncwarp();
            float4 e0 = ((const float4*)ers[eidx])[0];
            float4 e1 = ((const float4*)ers[eidx])[1];
            float rec = s_deb[j];
            rec = fmaf(e0.x, s_dew[0 * 32 + j], rec);
            rec = fmaf(e0.y, s_dew[1 * 32 + j], rec);
            rec = fmaf(e0.z, s_dew[2 * 32 + j], rec);
            rec = fmaf(e0.w, s_dew[3 * 32 + j], rec);
            rec = fmaf(e1.x, s_dew[4 * 32 + j], rec);
            rec = fmaf(e1.y, s_dew[5 * 32 + j], rec);
            rec = fmaf(e1.z, s_dew[6 * 32 + j], rec);
            rec = fmaf(e1.w, s_dew[7 * 32 + j], rec);
            out[OFF_RECON_EDGE + e * 32 + j] = rec;
            if (j < 3) {
                float4 gg = g_geo[e];
                float wz = fmaxf(q8 + s_misc[0], 0.f) * s_misc[2] +
                           fmaxf(q9 + s_misc[1], 0.f) * s_misc[3];
                float inv = 1.0f / (sqrtf(gg.w) + 1.0f);
                float dj = (j == 0) ? gg.x : (j == 1) ? gg.y : gg.z;
                atomicAdd(out + OFF_COORD + row * 3 + j, dj * inv * wz);
            }
        }
    }
}

// ---------------------------------------------------------------------------
// K_node: fused node layer-1 + layer-2 + epilogue.  256 threads, 2 nodes/iter.
// ---------------------------------------------------------------------------
__global__ __launch_bounds__(256) void k_node(
        const float* __restrict__ nw1, const float* __restrict__ nb1,
        const float* __restrict__ nf, const float* __restrict__ outc,
        const float* __restrict__ nw2, const float* __restrict__ nb2,
        const float* __restrict__ fnw, const float* __restrict__ fnb,
        const float* __restrict__ dnw, const float* __restrict__ dnb,
        float* __restrict__ out) {
    __shared__ __align__(16) float hs2[2][128];
    __shared__ float ps[2][2][8];
    int tid = threadIdx.x;
    int k = tid & 127, slot1 = tid >> 7, lane = tid & 31;
    float bias1 = nb1[k];
    float wc0 = nw1[96 * 128 + k], wc1 = nw1[97 * 128 + k], wc2 = nw1[98 * 128 + k];
    int slot2 = (tid >> 6) & 1, jj = tid & 63, half = (tid >> 5) & 1;
    float bias2 = nb2[jj];

    for (int n0 = blockIdx.x * 2; n0 < N_NODES; n0 += gridDim.x * 2) {
        int n = n0 + slot1;
        float xa = nf[n * 64 + lane];
        float xb = nf[n * 64 + 32 + lane];
        float xc = g_agg[n * 32 + lane];
        float h = bias1;
#pragma unroll
        for (int t = 0; t < 32; t++)
            h = fmaf(__shfl_sync(0xffffffffu, xa, t), __ldg(nw1 + t * 128 + k), h);
#pragma unroll
        for (int t = 0; t < 32; t++)
            h = fmaf(__shfl_sync(0xffffffffu, xb, t), __ldg(nw1 + (32 + t) * 128 + k), h);
#pragma unroll
        for (int t = 0; t < 32; t++)
            h = fmaf(__shfl_sync(0xffffffffu, xc, t), __ldg(nw1 + (64 + t) * 128 + k), h);
        h = fmaf(outc[n * 3 + 0], wc0, h);
        h = fmaf(outc[n * 3 + 1], wc1, h);
        h = fmaf(outc[n * 3 + 2], wc2, h);
        hs2[slot1][k] = fmaxf(h, 0.f);
        __syncthreads();

        int n2 = n0 + slot2;
        float acc = bias2;
        if (tid < 128) {
            const float4* hrow = (const float4*)hs2[slot2];
#pragma unroll 8
            for (int kq = 0; kq < 32; kq++) {
                float4 v = hrow[kq];
                acc = fmaf(v.x, __ldg(nw2 + (kq * 4 + 0) * 64 + jj), acc);
                acc = fmaf(v.y, __ldg(nw2 + (kq * 4 + 1) * 64 + jj), acc);
                acc = fmaf(v.z, __ldg(nw2 + (kq * 4 + 2) * 64 + jj), acc);
                acc = fmaf(v.w, __ldg(nw2 + (kq * 4 + 3) * 64 + jj), acc);
            }
            float p[8];
#pragma unroll
            for (int r = 0; r < 8; r++) p[r] = acc * __ldg(fnw + jj * 8 + r);
#pragma unroll
            for (int off = 16; off > 0; off >>= 1) {
#pragma unroll
                for (int r = 0; r < 8; r++) p[r] += __shfl_xor_sync(0xffffffffu, p[r], off);
            }
            if (lane == 0) {
#pragma unroll
                for (int r = 0; r < 8; r++) ps[slot2][half][r] = p[r];
            }
        }
        __syncthreads();
        if (tid < 128) {
            float er[8];
#pragma unroll
            for (int r = 0; r < 8; r++)
                er[r] = ps[slot2][0][r] + ps[slot2][1][r] + __ldg(fnb + r);
            if (jj == 0) {
                float4 v0 = make_float4(er[0], er[1], er[2], er[3]);
                float4 v1 = make_float4(er[4], er[5], er[6], er[7]);
                ((float4*)(out + OFF_NODE_EMB + (long)n2 * 8))[0] = v0;
                ((float4*)(out + OFF_NODE_EMB + (long)n2 * 8))[1] = v1;
                ((float4*)(g_emb + n2 * 8))[0] = v0;
                ((float4*)(g_emb + n2 * 8))[1] = v1;
                float rr = 0.f;
#pragma unroll
                for (int r = 0; r < 8; r++) rr = fmaf(er[r], er[r], rr);
                g_r[n2] = rr;
            }
            float rec = __ldg(dnb + jj);
#pragma unroll
            for (int r = 0; r < 8; r++) rec = fmaf(er[r], __ldg(dnw + r * 64 + jj), rec);
            out[OFF_RECON_NODE + (long)n2 * 64 + jj] = rec;
        }
        __syncthreads();
    }
}

// ---------------------------------------------------------------------------
// K_adj: 80 rows x 1024 cols per block; folded sigmoid (1 MUFU).
// Diagonal select hoisted: uniform nodiag flag skips the per-element
// compares for all threads whose column quad never meets the diagonal.
// ---------------------------------------------------------------------------
__global__ __launch_bounds__(256) void k_adj(float* __restrict__ out) {
    int tid = threadIdx.x;
    int j0 = blockIdx.x * 1024 + tid * 4;
    float ejs[4][8], cj[4];
#pragma unroll
    for (int q = 0; q < 4; q++) {
        int jx = j0 + q;
        if (jx < N_NODES) {
            float4 a = ((const float4*)(g_emb + jx * 8))[0];
            float4 b = ((const float4*)(g_emb + jx * 8))[1];
            ejs[q][0] = -3.f * a.x; ejs[q][1] = -3.f * a.y;
            ejs[q][2] = -3.f * a.z; ejs[q][3] = -3.f * a.w;
            ejs[q][4] = -3.f * b.x; ejs[q][5] = -3.f * b.y;
            ejs[q][6] = -3.f * b.z; ejs[q][7] = -3.f * b.w;
            cj[q] = fmaf(1.5f, g_r[jx], -0.5f);
        } else {
#pragma unroll
            for (int r = 0; r < 8; r++) ejs[q][r] = 0.f;
            cj[q] = -0.5f;
        }
    }
    int ibase = blockIdx.y * ADJ_ROWS;   // 125 * 80 == 10000 exactly
    // this thread's columns [j0, j0+4) meet the diagonal only if they
    // intersect the block's row window [ibase, ibase+ADJ_ROWS)
    bool nodiag = (j0 + 3 < ibase) || (j0 >= ibase + ADJ_ROWS);
    for (int ii = 0; ii < ADJ_ROWS; ii++) {
        int i = ibase + ii;
        float4 a = ((const float4*)(g_emb + i * 8))[0];
        float4 b = ((const float4*)(g_emb + i * 8))[1];
        float eiv[8] = {a.x, a.y, a.z, a.w, b.x, b.y, b.z, b.w};
        float ai = 1.5f * g_r[i];
        float res[4];
#pragma unroll
        for (int q = 0; q < 4; q++) {
            float acc = ai + cj[q];
#pragma unroll
            for (int r = 0; r < 8; r++) acc = fmaf(eiv[r], ejs[q][r], acc);
            float t;
            asm("tanh.approx.f32 %0, %1;" : "=f"(t) : "f"(acc));
            res[q] = fmaf(0.5f, t, 0.5f);
        }
        if (!nodiag) {
#pragma unroll
            for (int q = 0; q < 4; q++)
                if (j0 + q == i) res[q] = 0.f;
        }
        if (j0 < N_NODES) {
            __stcs((float4*)(out + OFF_ADJ + (long)i * N_NODES + j0),
                   make_float4(res[0], res[1], res[2], res[3]));
        }
    }
}

// ---------------------------------------------------------------------------
extern "C" void kernel_launch(void* const* d_in, const int* in_sizes, int n_in,
                              void* d_out, int out_size) {
    const float* nf     = (const float*)d_in[0];
    const int*   ei     = (const int*)  d_in[1];
    const float* ea     = (const float*)d_in[2];
    const float* coords = (const float*)d_in[3];
    const float* ew1    = (const float*)d_in[4];
    const float* eb1    = (const float*)d_in[5];
    const float* ew2    = (const float*)d_in[6];
    const float* eb2    = (const float*)d_in[7];
    const float* cw1    = (const float*)d_in[8];
    const float* cb1    = (const float*)d_in[9];
    const float* cw2    = (const float*)d_in[10];
    const float* nw1    = (const float*)d_in[11];
    const float* nb1    = (const float*)d_in[12];
    const float* nw2    = (const float*)d_in[13];
    const float* nb2    = (const float*)d_in[14];
    const float* fnw    = (const float*)d_in[15];
    const float* fnb    = (const float*)d_in[16];
    const float* few    = (const float*)d_in[17];
    const float* feb    = (const float*)d_in[18];
    const float* dnw    = (const float*)d_in[19];
    const float* dnb    = (const float*)d_in[20];
    const float* dew    = (const float*)d_in[21];
    const float* deb    = (const float*)d_in[22];
    float* out = (float*)d_out;

    k_pre<<<1184 + 2500, 128>>>(nf, ew1, eb1, ei, coords, out);
    k_edge_fused<<<592, 128>>>(ew1, ew2, eb2, cw1, cb1, cw2, few, feb, dew, deb,
                               ei, ea, out);
    k_node<<<592, 256>>>(nw1, nb1, nf, out + OFF_COORD, nw2, nb2,
                         fnw, fnb, dnw, dnb, out);
    dim3 gadj(10, N_NODES / ADJ_ROWS);
    k_adj<<<gadj, 256>>>(out);
}